// round 16
// baseline (speedup 1.0000x reference)
#include <cuda_runtime.h>
#include <math.h>

#define NSTK 6000
#define HID  1024
#define EMB  256
#define NH   32
#define HD   32
#define TOPK 200
#define BB   4
#define SS   128
#define NROWS (BB*NH*SS)          // 16384 (b,h,s) rows
#define OUT_OFF_ATTN (BB*SS*HID)               // 524288
#define OUT_OFF_ATTD (OUT_OFF_ATTN + (size_t)NROWS*TOPK)  // +3276800

// ---------------- scratch (__device__ globals: allocation-free) -------------
__device__ float g_T1[NSTK*HID];
__device__ float g_KV[NSTK*HID];
__device__ float g_K [NSTK*HID];
__device__ float g_V [NSTK*HID];
__device__ float g_H [(size_t)BB*NSTK*HID];      // gelu(rel_in@Wg1+bg1), 98 MB
__device__ float g_Q [BB*SS*HID];
__device__ float g_qc [BB*HID];
__device__ float g_qcp[BB*HID];
__device__ float g_gates[(size_t)BB*NSTK*NH];
__device__ float g_scores[(size_t)NROWS*NSTK];   // 393 MB
__device__ float g_ctx[BB*SS*HID];
__device__ float g_op [BB*SS*HID];

// Replicates jax gelu(approximate=False): x * (erf(x / sqrt(2)) + 1) / 2
__device__ __forceinline__ float gelu_ref(float x){
    float t = x / 1.41421356237309515f;
    return x * (erff(t) + 1.0f) * 0.5f;
}
__device__ __forceinline__ unsigned mono_f(float f){
    unsigned u=__float_as_uint(f);
    return (u & 0x80000000u) ? ~u : (u | 0x80000000u);
}
__device__ __forceinline__ float unmono_f(unsigned s){
    unsigned u = (s & 0x80000000u) ? (s ^ 0x80000000u) : ~s;
    return __uint_as_float(u);
}

// ---------------- packed f32x2 helpers (sm_103a) ---------------------------
__device__ __forceinline__ void ffma2(unsigned long long &d,
                                      unsigned long long a,
                                      unsigned long long b){
    asm("fma.rn.f32x2 %0, %1, %2, %0;" : "+l"(d) : "l"(a), "l"(b));
}
__device__ __forceinline__ unsigned long long dup2(float x){
    unsigned u = __float_as_uint(x);
    unsigned long long r;
    asm("mov.b64 %0, {%1, %1};" : "=l"(r) : "r"(u));
    return r;
}
__device__ __forceinline__ float lane0(unsigned long long v){
    return __uint_as_float((unsigned)v);
}
__device__ __forceinline__ float lane1(unsigned long long v){
    return __uint_as_float((unsigned)(v >> 32));
}

// ---------------- f32x2 GEMM: C = act(A@W + bias) ---------------------------
// BM=128, BN=128, BK=16, 256 thr, micro 4 row-pairs x 8 cols.
// LDS-wavefront bound analysis: A(8wf)+B(8wf) per warp-k-step for 2x FMAs of
// the 4-col version -> 33% fewer wavefronts per FMA. B kept plain f32 in smem
// (dup2 into u64 in registers; alu pipe has headroom).
// Per-output chain: serial FMA over k ascending -> bitwise == reference.
template<int ACT>
__global__ void __launch_bounds__(256) sgemm2(const float* __restrict__ A,
    const float* __restrict__ W, const float* __restrict__ bias,
    float* __restrict__ C, int M, int K, int N)
{
    __shared__ float As[16][128];                 // A^T tile (8 KB)
    __shared__ float Bs[16][128];                 // plain W tile (8 KB)
    const int bm = blockIdx.y*128, bn = blockIdx.x*128;
    const int tid = threadIdx.x;
    const int ty = tid>>4, tx = tid&15;
    const int a_row = tid>>1, a_k = (tid&1)*8;    // 2 float4 per thread
    const int b_row = tid>>4, b_lane = tid&15;    // cols b_lane*8 .. +7
    const bool a_ok = (bm + a_row) < M;
    const float* Ap = A + (size_t)(bm+a_row)*K + a_k;
    unsigned long long acc[4][8];
    #pragma unroll
    for (int p=0;p<4;p++)
        #pragma unroll
        for (int j=0;j<8;j++) acc[p][j] = 0ull;
    for (int k0=0; k0<K; k0+=16){
        float4 av0 = make_float4(0.f,0.f,0.f,0.f);
        float4 av1 = make_float4(0.f,0.f,0.f,0.f);
        if (a_ok){
            av0 = *(const float4*)(Ap + k0);
            av1 = *(const float4*)(Ap + k0 + 4);
        }
        As[a_k+0][a_row]=av0.x; As[a_k+1][a_row]=av0.y;
        As[a_k+2][a_row]=av0.z; As[a_k+3][a_row]=av0.w;
        As[a_k+4][a_row]=av1.x; As[a_k+5][a_row]=av1.y;
        As[a_k+6][a_row]=av1.z; As[a_k+7][a_row]=av1.w;
        {
            const float* wp = W + (size_t)(k0+b_row)*N + bn + b_lane*8;
            *(float4*)&Bs[b_row][b_lane*8]     = *(const float4*)(wp);
            *(float4*)&Bs[b_row][b_lane*8 + 4] = *(const float4*)(wp + 4);
        }
        __syncthreads();
        #pragma unroll
        for (int kk=0; kk<16; kk++){
            ulonglong2 a01 = *(const ulonglong2*)&As[kk][ty*8];
            ulonglong2 a23 = *(const ulonglong2*)&As[kk][ty*8+4];
            unsigned long long av[4] = {a01.x, a01.y, a23.x, a23.y};
            float4 b0 = *(const float4*)&Bs[kk][tx*8];
            float4 b1 = *(const float4*)&Bs[kk][tx*8+4];
            unsigned long long bv[8] = {dup2(b0.x), dup2(b0.y), dup2(b0.z), dup2(b0.w),
                                        dup2(b1.x), dup2(b1.y), dup2(b1.z), dup2(b1.w)};
            #pragma unroll
            for (int p=0;p<4;p++)
                #pragma unroll
                for (int j=0;j<8;j++) ffma2(acc[p][j], av[p], bv[j]);
        }
        __syncthreads();
    }
    #pragma unroll
    for (int p=0;p<4;p++){
        #pragma unroll
        for (int lane=0; lane<2; lane++){
            int row = bm + ty*8 + 2*p + lane;
            if (row >= M) continue;
            float v8[8];
            #pragma unroll
            for (int j=0;j<8;j++){
                float v = lane ? lane1(acc[p][j]) : lane0(acc[p][j]);
                if (bias) v += bias[bn + tx*8 + j];
                if (ACT==1) v = gelu_ref(v);
                v8[j] = v;
            }
            float* cp = C + (size_t)row*N + bn + tx*8;
            *(float4*)(cp)     = make_float4(v8[0],v8[1],v8[2],v8[3]);
            *(float4*)(cp + 4) = make_float4(v8[4],v8[5],v8[6],v8[7]);
        }
    }
}

// ---------------- small-M f32x2 GEMM: BM=32, BN=64, DOUBLE-BUFFERED ---------
// (round-11 proven WIN — unchanged)
template<int ACT>
__global__ void __launch_bounds__(256) sgemm_s32(const float* __restrict__ A,
    const float* __restrict__ W, const float* __restrict__ bias,
    float* __restrict__ C, int M, int K, int N)
{
    __shared__ float As[2][16][32];
    __shared__ unsigned long long Bs[2][16][64];
    const int bm = blockIdx.y*32, bn = blockIdx.x*64;
    const int tid = threadIdx.x;
    const int tr = tid>>4, tc = tid&15;
    const int b_row = tid>>4, b_c0 = (tid&15)*4;
    const int a_row = tid>>2, a_k = (tid&3)*4;
    const bool a_ld = (tid < 128);
    const bool a_ok = a_ld && (bm + a_row) < M;
    unsigned long long acc[4] = {0ull,0ull,0ull,0ull};

    float4 av = make_float4(0.f,0.f,0.f,0.f);
    if (a_ok) av = *(const float4*)(A + (size_t)(bm+a_row)*K + a_k);
    float4 bv = *(const float4*)(W + (size_t)b_row*N + bn + b_c0);
    if (a_ld){
        As[0][a_k+0][a_row]=av.x; As[0][a_k+1][a_row]=av.y;
        As[0][a_k+2][a_row]=av.z; As[0][a_k+3][a_row]=av.w;
    }
    Bs[0][b_row][0*16 + (tid&15)] = dup2(bv.x);
    Bs[0][b_row][1*16 + (tid&15)] = dup2(bv.y);
    Bs[0][b_row][2*16 + (tid&15)] = dup2(bv.z);
    Bs[0][b_row][3*16 + (tid&15)] = dup2(bv.w);
    __syncthreads();

    const int NT = K/16;
    int buf = 0;
    for (int t=0; t<NT; t++){
        float4 av2 = make_float4(0.f,0.f,0.f,0.f);
        float4 bv2 = make_float4(0.f,0.f,0.f,0.f);
        const bool have = (t+1 < NT);
        if (have){
            int k0 = (t+1)*16;
            if (a_ok) av2 = *(const float4*)(A + (size_t)(bm+a_row)*K + k0 + a_k);
            bv2 = *(const float4*)(W + (size_t)(k0+b_row)*N + bn + b_c0);
        }
        #pragma unroll
        for (int kk=0; kk<16; kk++){
            unsigned long long a2 = *(const unsigned long long*)&As[buf][kk][tr*2];
            #pragma unroll
            for (int j=0;j<4;j++) ffma2(acc[j], a2, Bs[buf][kk][j*16 + tc]);
        }
        if (have){
            int nb = buf^1;
            if (a_ld){
                As[nb][a_k+0][a_row]=av2.x; As[nb][a_k+1][a_row]=av2.y;
                As[nb][a_k+2][a_row]=av2.z; As[nb][a_k+3][a_row]=av2.w;
            }
            Bs[nb][b_row][0*16 + (tid&15)] = dup2(bv2.x);
            Bs[nb][b_row][1*16 + (tid&15)] = dup2(bv2.y);
            Bs[nb][b_row][2*16 + (tid&15)] = dup2(bv2.z);
            Bs[nb][b_row][3*16 + (tid&15)] = dup2(bv2.w);
            __syncthreads();
            buf = nb;
        }
    }
    #pragma unroll
    for (int lane=0; lane<2; lane++){
        int row = bm + tr*2 + lane;
        if (row >= M) continue;
        float4 v4; float* vp = (float*)&v4;
        #pragma unroll
        for (int j=0;j<4;j++){
            float v = lane ? lane1(acc[j]) : lane0(acc[j]);
            if (bias) v += bias[bn + tc*4 + j];
            if (ACT==1) v = gelu_ref(v);
            vp[j] = v;
        }
        *(float4*)(C + (size_t)row*N + bn + tc*4) = v4;
    }
}

// qcp[b,:] = qc[b,:] @ Wg1_top  (M=4: one thread per output, serial K chain)
__global__ void __launch_bounds__(1024) qcp_kernel(const float* __restrict__ qc,
    const float* __restrict__ W, float* __restrict__ qcp)
{
    __shared__ float a[HID];
    const int b = blockIdx.x;
    for (int i=threadIdx.x; i<HID; i+=blockDim.x) a[i] = qc[b*HID + i];
    __syncthreads();
    const int c = threadIdx.x;
    float acc = 0.f;
    #pragma unroll 8
    for (int k=0; k<HID; k++) acc = fmaf(a[k], W[(size_t)k*HID + c], acc);
    qcp[b*HID + c] = acc;
}

// query_combined[b] = mean_s(qf[b]) + KV[qid[b]]  (serial ascending sum)
__global__ void qc_kernel(const float* __restrict__ qf, const int* __restrict__ qid,
                          const float* __restrict__ KV, float* __restrict__ qc)
{
    int b = blockIdx.x;
    int sid = qid[b];
    for (int c = threadIdx.x; c < HID; c += blockDim.x){
        float s = 0.f;
        const float* p = qf + (size_t)b*SS*HID + c;
        #pragma unroll 4
        for (int t=0;t<SS;t++) s += p[(size_t)t*HID];
        qc[b*HID+c] = s*(1.0f/SS) + KV[(size_t)sid*HID + c];
    }
}

// H[b,n,:] = gelu( (qc-half serial chain = qcp[b,:]) continued serially over
// kv-half + bg1 ). f32x2, per-column acc init, 4 row-pairs x 8 cols (sgemm2).
__global__ void __launch_bounds__(256) gateh2(const float* __restrict__ KV,
    const float* __restrict__ Wlow, const float* __restrict__ qcp,
    const float* __restrict__ bg1, float* __restrict__ H)
{
    __shared__ float As[16][128];
    __shared__ float Bs[16][128];
    const int bm = blockIdx.y*128, bn = blockIdx.x*128;
    const int z  = blockIdx.z;
    const int tid = threadIdx.x;
    const int ty = tid>>4, tx = tid&15;
    const int a_row = tid>>1, a_k = (tid&1)*8;
    const int b_row = tid>>4, b_lane = tid&15;
    const bool a_ok = (bm + a_row) < NSTK;
    const float* Ap = KV + (size_t)(bm+a_row)*HID + a_k;
    unsigned long long acc[4][8];
    #pragma unroll
    for (int p=0;p<4;p++)
        #pragma unroll
        for (int j=0;j<8;j++) acc[p][j] = dup2(qcp[z*HID + bn + tx*8 + j]);
    for (int k0=0; k0<HID; k0+=16){
        float4 av0 = make_float4(0.f,0.f,0.f,0.f);
        float4 av1 = make_float4(0.f,0.f,0.f,0.f);
        if (a_ok){
            av0 = *(const float4*)(Ap + k0);
            av1 = *(const float4*)(Ap + k0 + 4);
        }
        As[a_k+0][a_row]=av0.x; As[a_k+1][a_row]=av0.y;
        As[a_k+2][a_row]=av0.z; As[a_k+3][a_row]=av0.w;
        As[a_k+4][a_row]=av1.x; As[a_k+5][a_row]=av1.y;
        As[a_k+6][a_row]=av1.z; As[a_k+7][a_row]=av1.w;
        {
            const float* wp = Wlow + (size_t)(k0+b_row)*HID + bn + b_lane*8;
            *(float4*)&Bs[b_row][b_lane*8]     = *(const float4*)(wp);
            *(float4*)&Bs[b_row][b_lane*8 + 4] = *(const float4*)(wp + 4);
        }
        __syncthreads();
        #pragma unroll
        for (int kk=0; kk<16; kk++){
            ulonglong2 a01 = *(const ulonglong2*)&As[kk][ty*8];
            ulonglong2 a23 = *(const ulonglong2*)&As[kk][ty*8+4];
            unsigned long long av[4] = {a01.x, a01.y, a23.x, a23.y};
            float4 b0 = *(const float4*)&Bs[kk][tx*8];
            float4 b1 = *(const float4*)&Bs[kk][tx*8+4];
            unsigned long long bv[8] = {dup2(b0.x), dup2(b0.y), dup2(b0.z), dup2(b0.w),
                                        dup2(b1.x), dup2(b1.y), dup2(b1.z), dup2(b1.w)};
            #pragma unroll
            for (int p=0;p<4;p++)
                #pragma unroll
                for (int j=0;j<8;j++) ffma2(acc[p][j], av[p], bv[j]);
        }
        __syncthreads();
    }
    #pragma unroll
    for (int p=0;p<4;p++){
        #pragma unroll
        for (int lane=0; lane<2; lane++){
            int row = bm + ty*8 + 2*p + lane;
            if (row >= NSTK) continue;
            float v8[8];
            #pragma unroll
            for (int j=0;j<8;j++){
                float v = lane ? lane1(acc[p][j]) : lane0(acc[p][j]);
                v8[j] = gelu_ref(v + bg1[bn + tx*8 + j]);
            }
            float* hp = H + ((size_t)z*NSTK + row)*HID + bn + tx*8;
            *(float4*)(hp)     = make_float4(v8[0],v8[1],v8[2],v8[3]);
            *(float4*)(hp + 4) = make_float4(v8[4],v8[5],v8[6],v8[7]);
        }
    }
}

// gates[row*32+h] = sigmoid( H[row,:] @ Wg2 + bg2 )[h], f32x2 row-pairs.
__global__ void __launch_bounds__(256) gates2_kernel(const float* __restrict__ H,
    const float* __restrict__ Wg2, const float* __restrict__ bg2,
    float* __restrict__ gates)
{
    __shared__ float As[32][64];
    __shared__ unsigned long long Ws[32][32];
    const int r0 = blockIdx.x*64;
    const int tid = threadIdx.x;
    const int a_row = tid>>2, a_k = (tid&3)*4;
    const float* hp = H + (size_t)(r0 + a_row)*HID;
    const int w_row = tid>>3, w_col = (tid&7)*4;
    const int ty = tid>>4, tx = tid&15;
    unsigned long long acc[2][2] = {{0ull,0ull},{0ull,0ull}};
    for (int k0=0; k0<HID; k0+=32){
        #pragma unroll
        for (int hh=0; hh<2; hh++){
            int kk = a_k + hh*16;
            float4 a4 = *(const float4*)(hp + k0 + kk);
            As[kk+0][a_row]=a4.x; As[kk+1][a_row]=a4.y;
            As[kk+2][a_row]=a4.z; As[kk+3][a_row]=a4.w;
        }
        float4 wv = *(const float4*)(Wg2 + (size_t)(k0+w_row)*NH + w_col);
        Ws[w_row][w_col+0]=dup2(wv.x); Ws[w_row][w_col+1]=dup2(wv.y);
        Ws[w_row][w_col+2]=dup2(wv.z); Ws[w_row][w_col+3]=dup2(wv.w);
        __syncthreads();
        #pragma unroll
        for (int kk=0; kk<32; kk++){
            ulonglong2 ap = *(const ulonglong2*)&As[kk][ty*4];
            unsigned long long av[2] = {ap.x, ap.y};
            unsigned long long b0 = Ws[kk][tx*2], b1 = Ws[kk][tx*2+1];
            ffma2(acc[0][0], av[0], b0); ffma2(acc[0][1], av[0], b1);
            ffma2(acc[1][0], av[1], b0); ffma2(acc[1][1], av[1], b1);
        }
        __syncthreads();
    }
    #pragma unroll
    for (int p=0;p<2;p++)
        #pragma unroll
        for (int lane=0; lane<2; lane++){
            int row = r0 + ty*4 + 2*p + lane;
            #pragma unroll
            for (int j=0;j<2;j++){
                int col = tx*2 + j;
                float v = (lane ? lane1(acc[p][j]) : lane0(acc[p][j])) + bg2[col];
                gates[(size_t)row*NH + col] = 1.0f/(1.0f + expf(-v));
            }
        }
}

// scores[(b*32+h)*128+s][n] = fl( fl(q.k / sqrt(32)) * gates[b,n,h] )
__global__ void __launch_bounds__(256) scores2_kernel(const float* __restrict__ Q,
    const float* __restrict__ Kb, const float* __restrict__ gates,
    float* __restrict__ scores)
{
    __shared__ float qs[HD][128];                  // 16 KB
    __shared__ unsigned long long ksd[HD][128];    // 32 KB (dup'd)
    const int n0 = blockIdx.x*128;
    const int bh = blockIdx.y;
    const int b = bh>>5, h = bh&31;
    const int tid = threadIdx.x;
    const int lrow = tid>>1;
    const int koff = (tid&1)*16;
    {
        const float* qp = Q + (size_t)(b*SS + lrow)*HID + h*HD + koff;
        #pragma unroll
        for(int t=0;t<4;t++){
            float4 v = *(const float4*)(qp + t*4);
            qs[koff+t*4+0][lrow]=v.x; qs[koff+t*4+1][lrow]=v.y;
            qs[koff+t*4+2][lrow]=v.z; qs[koff+t*4+3][lrow]=v.w;
        }
        int n = n0 + lrow;
        int sidx = (lrow&7)*16 + (lrow>>3);
        if (n < NSTK){
            const float* kp = Kb + (size_t)n*HID + h*HD + koff;
            #pragma unroll
            for(int t=0;t<4;t++){
                float4 v = *(const float4*)(kp + t*4);
                ksd[koff+t*4+0][sidx]=dup2(v.x); ksd[koff+t*4+1][sidx]=dup2(v.y);
                ksd[koff+t*4+2][sidx]=dup2(v.z); ksd[koff+t*4+3][sidx]=dup2(v.w);
            }
        } else {
            #pragma unroll
            for(int t=0;t<16;t++) ksd[koff+t][sidx]=0ull;
        }
    }
    __syncthreads();
    const int ty = tid>>4, tx = tid&15;
    unsigned long long acc[4][8];
    #pragma unroll
    for(int p=0;p<4;p++)
        #pragma unroll
        for(int j=0;j<8;j++) acc[p][j]=0ull;
    #pragma unroll
    for(int kk=0; kk<HD; kk++){
        ulonglong2 a01 = *(const ulonglong2*)&qs[kk][ty*8];
        ulonglong2 a23 = *(const ulonglong2*)&qs[kk][ty*8+4];
        unsigned long long av[4] = {a01.x, a01.y, a23.x, a23.y};
        unsigned long long bv[8];
        #pragma unroll
        for(int j=0;j<8;j++) bv[j] = ksd[kk][j*16 + tx];
        #pragma unroll
        for(int p=0;p<4;p++)
            #pragma unroll
            for(int j=0;j<8;j++) ffma2(acc[p][j], av[p], bv[j]);
    }
    float gv[8];
    #pragma unroll
    for(int j=0;j<8;j++){
        int n = n0 + tx*8 + j;
        gv[j] = (n < NSTK) ? gates[((size_t)b*NSTK + n)*NH + h] : 0.f;
    }
    const bool edge = (n0 + tx*8 + 7) >= NSTK;
    #pragma unroll
    for(int p=0;p<4;p++){
        #pragma unroll
        for(int lane=0; lane<2; lane++){
            int s = ty*8 + 2*p + lane;
            float* op = scores + ((size_t)bh*SS + s)*NSTK;
            float v8[8];
            #pragma unroll
            for(int j=0;j<8;j++){
                float d = lane ? lane1(acc[p][j]) : lane0(acc[p][j]);
                float sc = d / 5.656854249492381f;  // f32 div, round
                v8[j] = sc * gv[j];                  // f32 mul, round
            }
            if (!edge){
                *(float4*)(op + n0 + tx*8)     = make_float4(v8[0],v8[1],v8[2],v8[3]);
                *(float4*)(op + n0 + tx*8 + 4) = make_float4(v8[4],v8[5],v8[6],v8[7]);
            } else {
                #pragma unroll
                for(int j=0;j<8;j++){
                    int n = n0 + tx*8 + j;
                    if (n < NSTK) op[n] = v8[j];
                }
            }
        }
    }
}

// per-(b,h,s) row: exact top-200 (value desc, index asc), softmax, context.
// Round-11 proven version: plain histogram atomics (warp-aggregation schemes
// measured SLOWER on sm_103a — match_any and ballot-loop both regressed).
__global__ void __launch_bounds__(256) topk_kernel(const float* __restrict__ scores,
    const float* __restrict__ V, float* __restrict__ attn_out,
    float* __restrict__ attd_out, float* __restrict__ ctx)
{
    __shared__ float vals[NSTK];
    __shared__ unsigned hist[256];
    __shared__ unsigned long long cand[256];
    __shared__ float earr[256];
    __shared__ float red[256];
    __shared__ int   iarr[256];
    __shared__ float ctxp[8][32];
    __shared__ unsigned sh_prefix;
    __shared__ int sh_rem, sh_cnt;

    const int r = blockIdx.x;
    const int s = r & 127, h = (r>>7)&31, b = r>>12;
    const int tid = threadIdx.x;
    const float* rowp = scores + (size_t)r*NSTK;
    {   // vectorized row load: 6000 = 1500 float4
        const float4* rp4 = (const float4*)rowp;
        for (int i=tid; i<NSTK/4; i+=256)
            *(float4*)&vals[i*4] = rp4[i];
    }
    if (tid==0){ sh_prefix=0u; sh_rem=TOPK; }
    __syncthreads();

    // 4-pass radix select: exact key of 200th-largest
    #pragma unroll
    for (int pass=0; pass<4; pass++){
        const int shift = 24 - pass*8;
        hist[tid]=0u;
        __syncthreads();
        unsigned pref = sh_prefix;
        for (int i=tid;i<NSTK;i+=256){
            unsigned k = mono_f(vals[i]);
            unsigned hi = (pass==0) ? 0u : (k >> (shift+8));
            if (hi == pref)
                atomicAdd(&hist[(k>>shift)&0xFFu], 1u);
        }
        __syncthreads();
        if (tid==0){
            int rem = sh_rem; int bsel = 255;
            for (; bsel>0; bsel--){
                int c = (int)hist[bsel];
                if (c >= rem) break;
                rem -= c;
            }
            sh_prefix = (pref<<8) | (unsigned)bsel;
            sh_rem = rem;
        }
        __syncthreads();
    }
    const unsigned T = sh_prefix;
    if (tid==0) sh_cnt=0;
    cand[tid] = 0xFFFFFFFFFFFFFFFFull;
    __syncthreads();
    for (int i=tid;i<NSTK;i+=256){
        unsigned k = mono_f(vals[i]);
        if (k >= T){
            int p = atomicAdd(&sh_cnt,1);
            if (p < 256) cand[p] = (((unsigned long long)(~k))<<32) | (unsigned)i;
        }
    }
    __syncthreads();
    // bitonic sort 256 u64 ascending -> (value desc, index asc)
    for (int k2=2; k2<=256; k2<<=1){
        for (int j=k2>>1; j>0; j>>=1){
            int ixj = tid ^ j;
            if (ixj > tid){
                unsigned long long A=cand[tid], Bv=cand[ixj];
                bool up = ((tid & k2)==0);
                if (up ? (A > Bv) : (A < Bv)){ cand[tid]=Bv; cand[ixj]=A; }
            }
            __syncthreads();
        }
    }
    // softmax over top 200
    float v0 = unmono_f(~(unsigned)(cand[0]>>32));
    float e = 0.f; int idx = 0;
    if (tid < TOPK){
        unsigned long long c = cand[tid];
        idx = (int)(unsigned)(c & 0xFFFFFFFFull);
        float v = unmono_f(~(unsigned)(c>>32));
        e = expf(v - v0);
    }
    earr[tid]=e; red[tid]=e; iarr[tid]=idx;
    __syncthreads();
    for (int st=128; st>0; st>>=1){
        if (tid < st) red[tid] += red[tid+st];
        __syncthreads();
    }
    float inv = 1.0f/red[0];
    float a = e*inv;
    if (tid < TOPK){
        attn_out[(size_t)r*TOPK + tid] = a;
        if (s == SS-1) attd_out[(size_t)(b*NH + h)*TOPK + tid] = (float)idx;
    }
    __syncthreads();
    earr[tid] = a;
    __syncthreads();
    // context: c[d] = sum_k a_k * V[idx_k, h, d]
    int w = tid>>5, lane = tid&31;
    float accd = 0.f;
    for (int k2=w; k2<TOPK; k2+=8)
        accd = fmaf(earr[k2], V[(size_t)iarr[k2]*HID + h*HD + lane], accd);
    ctxp[w][lane]=accd;
    __syncthreads();
    if (tid < 32){
        float sum2 = 0.f;
        #pragma unroll
        for (int w2=0; w2<8; w2++) sum2 += ctxp[w2][tid];
        ctx[(size_t)(b*SS + s)*HID + h*HD + tid] = sum2;
    }
}

// out = LN(qf + oproj) * g + b
__global__ void __launch_bounds__(256) ln_kernel(const float* __restrict__ qf,
    const float* __restrict__ O, const float* __restrict__ g,
    const float* __restrict__ be, float* __restrict__ out)
{
    __shared__ float red[256];
    const int r = blockIdx.x, tid = threadIdx.x;
    float x[4];
    #pragma unroll
    for (int i=0;i<4;i++){
        int c = tid + i*256;
        x[i] = qf[(size_t)r*HID + c] + O[(size_t)r*HID + c];
    }
    float sm = x[0]+x[1]+x[2]+x[3];
    red[tid]=sm; __syncthreads();
    for (int st=128; st>0; st>>=1){ if (tid<st) red[tid]+=red[tid+st]; __syncthreads(); }
    float mu = red[0]*(1.0f/HID);
    __syncthreads();
    float vs = 0.f;
    #pragma unroll
    for (int i=0;i<4;i++){ float d=x[i]-mu; vs += d*d; }
    red[tid]=vs; __syncthreads();
    for (int st=128; st>0; st>>=1){ if (tid<st) red[tid]+=red[tid+st]; __syncthreads(); }
    float rstd = rsqrtf(red[0]*(1.0f/HID) + 1e-5f);
    #pragma unroll
    for (int i=0;i<4;i++){
        int c = tid + i*256;
        out[(size_t)r*HID + c] = (x[i]-mu)*rstd*g[c] + be[c];
    }
}

extern "C" void kernel_launch(void* const* d_in, const int* in_sizes, int n_in,
                              void* d_out, int out_size)
{
    const float* qf  = (const float*)d_in[0];
    const int*   qid = (const int*)  d_in[1];
    const float* emb = (const float*)d_in[2];
    const float* pW1 = (const float*)d_in[3];
    const float* pb1 = (const float*)d_in[4];
    const float* pW2 = (const float*)d_in[5];
    const float* pb2 = (const float*)d_in[6];
    const float* Wq  = (const float*)d_in[7];
    const float* bq  = (const float*)d_in[8];
    const float* Wk  = (const float*)d_in[9];
    const float* bk  = (const float*)d_in[10];
    const float* Wv  = (const float*)d_in[11];
    const float* bv  = (const float*)d_in[12];
    const float* Wo  = (const float*)d_in[13];
    const float* bo  = (const float*)d_in[14];
    const float* Wg1 = (const float*)d_in[15];
    const float* bg1 = (const float*)d_in[16];
    const float* Wg2 = (const float*)d_in[17];
    const float* bg2 = (const float*)d_in[18];
    const float* lng = (const float*)d_in[19];
    const float* lnb = (const float*)d_in[20];
    float* out = (float*)d_out;

    float *T1,*KV,*Kb,*Vb,*Hh,*Qm,*qc,*qcp,*gates,*scores,*ctx,*op;
    cudaGetSymbolAddress((void**)&T1,    g_T1);
    cudaGetSymbolAddress((void**)&KV,    g_KV);
    cudaGetSymbolAddress((void**)&Kb,    g_K);
    cudaGetSymbolAddress((void**)&Vb,    g_V);
    cudaGetSymbolAddress((void**)&Hh,    g_H);
    cudaGetSymbolAddress((void**)&Qm,    g_Q);
    cudaGetSymbolAddress((void**)&qc,    g_qc);
    cudaGetSymbolAddress((void**)&qcp,   g_qcp);
    cudaGetSymbolAddress((void**)&gates, g_gates);
    cudaGetSymbolAddress((void**)&scores,g_scores);
    cudaGetSymbolAddress((void**)&ctx,   g_ctx);
    cudaGetSymbolAddress((void**)&op,    g_op);

    const int GY = (NSTK + 127)/128;   // 47
    const int GX = HID/128;            // 8

    // embed_proj(stock_embed): T1 = gelu(E@pW1+pb1); KV = T1@pW2+pb2
    sgemm2<1><<<dim3(GX,GY),256>>>(emb, pW1, pb1, T1, NSTK, EMB, HID);
    sgemm2<0><<<dim3(GX,GY),256>>>(T1,  pW2, pb2, KV, NSTK, HID, HID);
    // K / V projections (score-critical serial chains)
    sgemm2<0><<<dim3(GX,GY),256>>>(KV, Wk, bk, Kb, NSTK, HID, HID);
    sgemm2<0><<<dim3(GX,GY),256>>>(KV, Wv, bv, Vb, NSTK, HID, HID);
    // Q projection: small-M path (M=512), double-buffered
    sgemm_s32<0><<<dim3(16,16),256>>>(qf, Wq, bq, Qm, BB*SS, HID, HID);
    // query_combined, qc-half serial chain (no bias — bias joins after kv-half)
    qc_kernel<<<BB,256>>>(qf, qid, KV, qc);
    qcp_kernel<<<BB,1024>>>(qc, Wg1, qcp);
    // full gate chain: continue qcp serially over kv-half, +bg1, gelu
    gateh2<<<dim3(GX,GY,BB),256>>>(KV, Wg1 + (size_t)HID*HID, qcp, bg1, Hh);
    // gate stage 2: H @ Wg2 + bg2 -> sigmoid
    gates2_kernel<<<(BB*NSTK)/64,256>>>(Hh, Wg2, bg2, gates);
    // scores (two-step rounding: /sqrt(32) then *gate)
    scores2_kernel<<<dim3((NSTK+127)/128, BB*NH),256>>>(Qm, Kb, gates, scores);
    // top-k + softmax + context (+ attn / attended outputs)
    topk_kernel<<<NROWS,256>>>(scores, Vb, out + OUT_OFF_ATTN, out + OUT_OFF_ATTD, ctx);
    // output projection + residual + layernorm: small-M path (M=512), double-buffered
    sgemm_s32<0><<<dim3(16,16),256>>>(ctx, Wo, bo, op, BB*SS, HID, HID);
    ln_kernel<<<BB*SS,256>>>(qf, op, lng, lnb, out);
}

// round 17
// speedup vs baseline: 1.1293x; 1.1293x over previous
#include <cuda_runtime.h>
#include <math.h>

#define NSTK 6000
#define HID  1024
#define EMB  256
#define NH   32
#define HD   32
#define TOPK 200
#define BB   4
#define SS   128
#define NROWS (BB*NH*SS)          // 16384 (b,h,s) rows
#define OUT_OFF_ATTN (BB*SS*HID)               // 524288
#define OUT_OFF_ATTD (OUT_OFF_ATTN + (size_t)NROWS*TOPK)  // +3276800

// ---------------- scratch (__device__ globals: allocation-free) -------------
__device__ float g_T1[NSTK*HID];
__device__ float g_KV[NSTK*HID];
__device__ float g_K [NSTK*HID];
__device__ float g_V [NSTK*HID];
__device__ float g_H [(size_t)BB*NSTK*HID];      // gelu(rel_in@Wg1+bg1), 98 MB
__device__ float g_Q [BB*SS*HID];
__device__ float g_qc [BB*HID];
__device__ float g_qcp[BB*HID];
__device__ float g_gates[(size_t)BB*NSTK*NH];
__device__ float g_scores[(size_t)NROWS*NSTK];   // 393 MB
__device__ float g_ctx[BB*SS*HID];
__device__ float g_op [BB*SS*HID];

// Replicates jax gelu(approximate=False): x * (erf(x / sqrt(2)) + 1) / 2
__device__ __forceinline__ float gelu_ref(float x){
    float t = x / 1.41421356237309515f;
    return x * (erff(t) + 1.0f) * 0.5f;
}
__device__ __forceinline__ unsigned mono_f(float f){
    unsigned u=__float_as_uint(f);
    return (u & 0x80000000u) ? ~u : (u | 0x80000000u);
}
__device__ __forceinline__ float unmono_f(unsigned s){
    unsigned u = (s & 0x80000000u) ? (s ^ 0x80000000u) : ~s;
    return __uint_as_float(u);
}

// ---------------- packed f32x2 helpers (sm_103a) ---------------------------
__device__ __forceinline__ void ffma2(unsigned long long &d,
                                      unsigned long long a,
                                      unsigned long long b){
    asm("fma.rn.f32x2 %0, %1, %2, %0;" : "+l"(d) : "l"(a), "l"(b));
}
__device__ __forceinline__ unsigned long long dup2(float x){
    unsigned u = __float_as_uint(x);
    unsigned long long r;
    asm("mov.b64 %0, {%1, %1};" : "=l"(r) : "r"(u));
    return r;
}
__device__ __forceinline__ float lane0(unsigned long long v){
    return __uint_as_float((unsigned)v);
}
__device__ __forceinline__ float lane1(unsigned long long v){
    return __uint_as_float((unsigned)(v >> 32));
}

// ---------------- f32x2 GEMM: C = act(A@W + bias) ---------------------------
// ROUND-15 PROVEN BEST: BM=128, BN=64, BK=16, 256 thr, 4 row-pairs x 4 cols.
// W tile plain f32 in smem (dup2 into u64 in registers; alu has headroom).
// (8-col variant blacklisted: 32 u64 accs -> 2 CTA/SM, regressed twice.)
// Per-output chain: serial FMA over k ascending -> bitwise == reference.
template<int ACT>
__global__ void __launch_bounds__(256) sgemm2(const float* __restrict__ A,
    const float* __restrict__ W, const float* __restrict__ bias,
    float* __restrict__ C, int M, int K, int N)
{
    __shared__ float As[16][128];                 // A^T tile (8 KB)
    __shared__ float Bs[16][64];                  // plain W tile (4 KB)
    const int bm = blockIdx.y*128, bn = blockIdx.x*64;
    const int tid = threadIdx.x;
    const int tr = tid>>4, tc = tid&15;
    const int a_row = tid>>1, a_k = (tid&1)*8;    // 2 float4 per thread
    const int b_row = tid>>4, b_lane = tid&15;    // cols b_lane*4 .. +3
    const bool a_ok = (bm + a_row) < M;
    const float* Ap = A + (size_t)(bm+a_row)*K + a_k;
    unsigned long long acc[4][4];
    #pragma unroll
    for (int p=0;p<4;p++)
        #pragma unroll
        for (int j=0;j<4;j++) acc[p][j] = 0ull;
    for (int k0=0; k0<K; k0+=16){
        float4 av0 = make_float4(0.f,0.f,0.f,0.f);
        float4 av1 = make_float4(0.f,0.f,0.f,0.f);
        if (a_ok){
            av0 = *(const float4*)(Ap + k0);
            av1 = *(const float4*)(Ap + k0 + 4);
        }
        As[a_k+0][a_row]=av0.x; As[a_k+1][a_row]=av0.y;
        As[a_k+2][a_row]=av0.z; As[a_k+3][a_row]=av0.w;
        As[a_k+4][a_row]=av1.x; As[a_k+5][a_row]=av1.y;
        As[a_k+6][a_row]=av1.z; As[a_k+7][a_row]=av1.w;
        *(float4*)&Bs[b_row][b_lane*4] =
            *(const float4*)(W + (size_t)(k0+b_row)*N + bn + b_lane*4);
        __syncthreads();
        #pragma unroll
        for (int kk=0; kk<16; kk++){
            ulonglong2 a01 = *(const ulonglong2*)&As[kk][tr*8];
            ulonglong2 a23 = *(const ulonglong2*)&As[kk][tr*8+4];
            unsigned long long av[4] = {a01.x, a01.y, a23.x, a23.y};
            float4 bq = *(const float4*)&Bs[kk][tc*4];
            unsigned long long bv2[4] = {dup2(bq.x), dup2(bq.y),
                                         dup2(bq.z), dup2(bq.w)};
            #pragma unroll
            for (int p=0;p<4;p++)
                #pragma unroll
                for (int j=0;j<4;j++) ffma2(acc[p][j], av[p], bv2[j]);
        }
        __syncthreads();
    }
    #pragma unroll
    for (int p=0;p<4;p++){
        #pragma unroll
        for (int lane=0; lane<2; lane++){
            int row = bm + tr*8 + 2*p + lane;
            if (row >= M) continue;
            float4 v4; float* vp = (float*)&v4;
            #pragma unroll
            for (int j=0;j<4;j++){
                float v = lane ? lane1(acc[p][j]) : lane0(acc[p][j]);
                if (bias) v += bias[bn + tc*4 + j];
                if (ACT==1) v = gelu_ref(v);
                vp[j] = v;
            }
            *(float4*)(C + (size_t)row*N + bn + tc*4) = v4;
        }
    }
}

// ---------------- small-M f32x2 GEMM: BM=32, BN=64, DOUBLE-BUFFERED ---------
// (round-11 proven WIN — unchanged)
template<int ACT>
__global__ void __launch_bounds__(256) sgemm_s32(const float* __restrict__ A,
    const float* __restrict__ W, const float* __restrict__ bias,
    float* __restrict__ C, int M, int K, int N)
{
    __shared__ float As[2][16][32];
    __shared__ unsigned long long Bs[2][16][64];
    const int bm = blockIdx.y*32, bn = blockIdx.x*64;
    const int tid = threadIdx.x;
    const int tr = tid>>4, tc = tid&15;
    const int b_row = tid>>4, b_c0 = (tid&15)*4;
    const int a_row = tid>>2, a_k = (tid&3)*4;
    const bool a_ld = (tid < 128);
    const bool a_ok = a_ld && (bm + a_row) < M;
    unsigned long long acc[4] = {0ull,0ull,0ull,0ull};

    float4 av = make_float4(0.f,0.f,0.f,0.f);
    if (a_ok) av = *(const float4*)(A + (size_t)(bm+a_row)*K + a_k);
    float4 bv = *(const float4*)(W + (size_t)b_row*N + bn + b_c0);
    if (a_ld){
        As[0][a_k+0][a_row]=av.x; As[0][a_k+1][a_row]=av.y;
        As[0][a_k+2][a_row]=av.z; As[0][a_k+3][a_row]=av.w;
    }
    Bs[0][b_row][0*16 + (tid&15)] = dup2(bv.x);
    Bs[0][b_row][1*16 + (tid&15)] = dup2(bv.y);
    Bs[0][b_row][2*16 + (tid&15)] = dup2(bv.z);
    Bs[0][b_row][3*16 + (tid&15)] = dup2(bv.w);
    __syncthreads();

    const int NT = K/16;
    int buf = 0;
    for (int t=0; t<NT; t++){
        float4 av2 = make_float4(0.f,0.f,0.f,0.f);
        float4 bv2 = make_float4(0.f,0.f,0.f,0.f);
        const bool have = (t+1 < NT);
        if (have){
            int k0 = (t+1)*16;
            if (a_ok) av2 = *(const float4*)(A + (size_t)(bm+a_row)*K + k0 + a_k);
            bv2 = *(const float4*)(W + (size_t)(k0+b_row)*N + bn + b_c0);
        }
        #pragma unroll
        for (int kk=0; kk<16; kk++){
            unsigned long long a2 = *(const unsigned long long*)&As[buf][kk][tr*2];
            #pragma unroll
            for (int j=0;j<4;j++) ffma2(acc[j], a2, Bs[buf][kk][j*16 + tc]);
        }
        if (have){
            int nb = buf^1;
            if (a_ld){
                As[nb][a_k+0][a_row]=av2.x; As[nb][a_k+1][a_row]=av2.y;
                As[nb][a_k+2][a_row]=av2.z; As[nb][a_k+3][a_row]=av2.w;
            }
            Bs[nb][b_row][0*16 + (tid&15)] = dup2(bv2.x);
            Bs[nb][b_row][1*16 + (tid&15)] = dup2(bv2.y);
            Bs[nb][b_row][2*16 + (tid&15)] = dup2(bv2.z);
            Bs[nb][b_row][3*16 + (tid&15)] = dup2(bv2.w);
            __syncthreads();
            buf = nb;
        }
    }
    #pragma unroll
    for (int lane=0; lane<2; lane++){
        int row = bm + tr*2 + lane;
        if (row >= M) continue;
        float4 v4; float* vp = (float*)&v4;
        #pragma unroll
        for (int j=0;j<4;j++){
            float v = lane ? lane1(acc[j]) : lane0(acc[j]);
            if (bias) v += bias[bn + tc*4 + j];
            if (ACT==1) v = gelu_ref(v);
            vp[j] = v;
        }
        *(float4*)(C + (size_t)row*N + bn + tc*4) = v4;
    }
}

// qcp[b,:] = qc[b,:] @ Wg1_top  (M=4: one thread per output, serial K chain)
__global__ void __launch_bounds__(1024) qcp_kernel(const float* __restrict__ qc,
    const float* __restrict__ W, float* __restrict__ qcp)
{
    __shared__ float a[HID];
    const int b = blockIdx.x;
    for (int i=threadIdx.x; i<HID; i+=blockDim.x) a[i] = qc[b*HID + i];
    __syncthreads();
    const int c = threadIdx.x;
    float acc = 0.f;
    #pragma unroll 8
    for (int k=0; k<HID; k++) acc = fmaf(a[k], W[(size_t)k*HID + c], acc);
    qcp[b*HID + c] = acc;
}

// query_combined[b] = mean_s(qf[b]) + KV[qid[b]]  (serial ascending sum)
__global__ void qc_kernel(const float* __restrict__ qf, const int* __restrict__ qid,
                          const float* __restrict__ KV, float* __restrict__ qc)
{
    int b = blockIdx.x;
    int sid = qid[b];
    for (int c = threadIdx.x; c < HID; c += blockDim.x){
        float s = 0.f;
        const float* p = qf + (size_t)b*SS*HID + c;
        #pragma unroll 4
        for (int t=0;t<SS;t++) s += p[(size_t)t*HID];
        qc[b*HID+c] = s*(1.0f/SS) + KV[(size_t)sid*HID + c];
    }
}

// H[b,n,:] = gelu( (qc-half serial chain = qcp[b,:]) continued serially over
// kv-half + bg1 ). f32x2, per-column acc init, plain-f32 B (round-15 config).
__global__ void __launch_bounds__(256) gateh2(const float* __restrict__ KV,
    const float* __restrict__ Wlow, const float* __restrict__ qcp,
    const float* __restrict__ bg1, float* __restrict__ H)
{
    __shared__ float As[16][128];
    __shared__ float Bs[16][64];
    const int bm = blockIdx.y*128, bn = blockIdx.x*64;
    const int z  = blockIdx.z;
    const int tid = threadIdx.x;
    const int tr = tid>>4, tc = tid&15;
    const int a_row = tid>>1, a_k = (tid&1)*8;
    const int b_row = tid>>4, b_lane = tid&15;
    const bool a_ok = (bm + a_row) < NSTK;
    const float* Ap = KV + (size_t)(bm+a_row)*HID + a_k;
    unsigned long long acc[4][4];
    #pragma unroll
    for (int p=0;p<4;p++)
        #pragma unroll
        for (int j=0;j<4;j++) acc[p][j] = dup2(qcp[z*HID + bn + tc*4 + j]);
    for (int k0=0; k0<HID; k0+=16){
        float4 av0 = make_float4(0.f,0.f,0.f,0.f);
        float4 av1 = make_float4(0.f,0.f,0.f,0.f);
        if (a_ok){
            av0 = *(const float4*)(Ap + k0);
            av1 = *(const float4*)(Ap + k0 + 4);
        }
        As[a_k+0][a_row]=av0.x; As[a_k+1][a_row]=av0.y;
        As[a_k+2][a_row]=av0.z; As[a_k+3][a_row]=av0.w;
        As[a_k+4][a_row]=av1.x; As[a_k+5][a_row]=av1.y;
        As[a_k+6][a_row]=av1.z; As[a_k+7][a_row]=av1.w;
        *(float4*)&Bs[b_row][b_lane*4] =
            *(const float4*)(Wlow + (size_t)(k0+b_row)*HID + bn + b_lane*4);
        __syncthreads();
        #pragma unroll
        for (int kk=0; kk<16; kk++){
            ulonglong2 a01 = *(const ulonglong2*)&As[kk][tr*8];
            ulonglong2 a23 = *(const ulonglong2*)&As[kk][tr*8+4];
            unsigned long long av[4] = {a01.x, a01.y, a23.x, a23.y};
            float4 bq = *(const float4*)&Bs[kk][tc*4];
            unsigned long long bv2[4] = {dup2(bq.x), dup2(bq.y),
                                         dup2(bq.z), dup2(bq.w)};
            #pragma unroll
            for (int p=0;p<4;p++)
                #pragma unroll
                for (int j=0;j<4;j++) ffma2(acc[p][j], av[p], bv2[j]);
        }
        __syncthreads();
    }
    #pragma unroll
    for (int p=0;p<4;p++){
        #pragma unroll
        for (int lane=0; lane<2; lane++){
            int row = bm + tr*8 + 2*p + lane;
            if (row >= NSTK) continue;
            float4 v4; float* vp = (float*)&v4;
            #pragma unroll
            for (int j=0;j<4;j++){
                float v = lane ? lane1(acc[p][j]) : lane0(acc[p][j]);
                vp[j] = gelu_ref(v + bg1[bn + tc*4 + j]);
            }
            *(float4*)(H + ((size_t)z*NSTK + row)*HID + bn + tc*4) = v4;
        }
    }
}

// gates[row*32+h] = sigmoid( H[row,:] @ Wg2 + bg2 )[h], f32x2 row-pairs.
__global__ void __launch_bounds__(256) gates2_kernel(const float* __restrict__ H,
    const float* __restrict__ Wg2, const float* __restrict__ bg2,
    float* __restrict__ gates)
{
    __shared__ float As[32][64];
    __shared__ unsigned long long Ws[32][32];
    const int r0 = blockIdx.x*64;
    const int tid = threadIdx.x;
    const int a_row = tid>>2, a_k = (tid&3)*4;
    const float* hp = H + (size_t)(r0 + a_row)*HID;
    const int w_row = tid>>3, w_col = (tid&7)*4;
    const int ty = tid>>4, tx = tid&15;
    unsigned long long acc[2][2] = {{0ull,0ull},{0ull,0ull}};
    for (int k0=0; k0<HID; k0+=32){
        #pragma unroll
        for (int hh=0; hh<2; hh++){
            int kk = a_k + hh*16;
            float4 a4 = *(const float4*)(hp + k0 + kk);
            As[kk+0][a_row]=a4.x; As[kk+1][a_row]=a4.y;
            As[kk+2][a_row]=a4.z; As[kk+3][a_row]=a4.w;
        }
        float4 wv = *(const float4*)(Wg2 + (size_t)(k0+w_row)*NH + w_col);
        Ws[w_row][w_col+0]=dup2(wv.x); Ws[w_row][w_col+1]=dup2(wv.y);
        Ws[w_row][w_col+2]=dup2(wv.z); Ws[w_row][w_col+3]=dup2(wv.w);
        __syncthreads();
        #pragma unroll
        for (int kk=0; kk<32; kk++){
            ulonglong2 ap = *(const ulonglong2*)&As[kk][ty*4];
            unsigned long long av[2] = {ap.x, ap.y};
            unsigned long long b0 = Ws[kk][tx*2], b1 = Ws[kk][tx*2+1];
            ffma2(acc[0][0], av[0], b0); ffma2(acc[0][1], av[0], b1);
            ffma2(acc[1][0], av[1], b0); ffma2(acc[1][1], av[1], b1);
        }
        __syncthreads();
    }
    #pragma unroll
    for (int p=0;p<2;p++)
        #pragma unroll
        for (int lane=0; lane<2; lane++){
            int row = r0 + ty*4 + 2*p + lane;
            #pragma unroll
            for (int j=0;j<2;j++){
                int col = tx*2 + j;
                float v = (lane ? lane1(acc[p][j]) : lane0(acc[p][j])) + bg2[col];
                gates[(size_t)row*NH + col] = 1.0f/(1.0f + expf(-v));
            }
        }
}

// scores[(b*32+h)*128+s][n] = fl( fl(q.k / sqrt(32)) * gates[b,n,h] )
// K tile now PLAIN f32 (round-15 transformation): smem 48->32 KB, B-side
// wavefronts halved (two LDS.128 per thread instead of 8 LDS.64); dup2 into
// u64 in registers. bv[j] = ks[kk][tx*8+j] reproduces the old swizzle's
// n = tx*8+j mapping exactly -> bitwise-identical scores.
__global__ void __launch_bounds__(256) scores2_kernel(const float* __restrict__ Q,
    const float* __restrict__ Kb, const float* __restrict__ gates,
    float* __restrict__ scores)
{
    __shared__ float qs[HD][128];                  // 16 KB
    __shared__ float ks[HD][128];                  // 16 KB (plain f32)
    const int n0 = blockIdx.x*128;
    const int bh = blockIdx.y;
    const int b = bh>>5, h = bh&31;
    const int tid = threadIdx.x;
    const int lrow = tid>>1;
    const int koff = (tid&1)*16;
    {
        const float* qp = Q + (size_t)(b*SS + lrow)*HID + h*HD + koff;
        #pragma unroll
        for(int t=0;t<4;t++){
            float4 v = *(const float4*)(qp + t*4);
            qs[koff+t*4+0][lrow]=v.x; qs[koff+t*4+1][lrow]=v.y;
            qs[koff+t*4+2][lrow]=v.z; qs[koff+t*4+3][lrow]=v.w;
        }
        int n = n0 + lrow;
        if (n < NSTK){
            const float* kp = Kb + (size_t)n*HID + h*HD + koff;
            #pragma unroll
            for(int t=0;t<4;t++){
                float4 v = *(const float4*)(kp + t*4);
                ks[koff+t*4+0][lrow]=v.x; ks[koff+t*4+1][lrow]=v.y;
                ks[koff+t*4+2][lrow]=v.z; ks[koff+t*4+3][lrow]=v.w;
            }
        } else {
            #pragma unroll
            for(int t=0;t<16;t++) ks[koff+t][lrow]=0.f;
        }
    }
    __syncthreads();
    const int ty = tid>>4, tx = tid&15;
    unsigned long long acc[4][8];
    #pragma unroll
    for(int p=0;p<4;p++)
        #pragma unroll
        for(int j=0;j<8;j++) acc[p][j]=0ull;
    #pragma unroll
    for(int kk=0; kk<HD; kk++){
        ulonglong2 a01 = *(const ulonglong2*)&qs[kk][ty*8];
        ulonglong2 a23 = *(const ulonglong2*)&qs[kk][ty*8+4];
        unsigned long long av[4] = {a01.x, a01.y, a23.x, a23.y};
        float4 b0 = *(const float4*)&ks[kk][tx*8];
        float4 b1 = *(const float4*)&ks[kk][tx*8+4];
        unsigned long long bv[8] = {dup2(b0.x), dup2(b0.y), dup2(b0.z), dup2(b0.w),
                                    dup2(b1.x), dup2(b1.y), dup2(b1.z), dup2(b1.w)};
        #pragma unroll
        for(int p=0;p<4;p++)
            #pragma unroll
            for(int j=0;j<8;j++) ffma2(acc[p][j], av[p], bv[j]);
    }
    float gv[8];
    #pragma unroll
    for(int j=0;j<8;j++){
        int n = n0 + tx*8 + j;
        gv[j] = (n < NSTK) ? gates[((size_t)b*NSTK + n)*NH + h] : 0.f;
    }
    const bool edge = (n0 + tx*8 + 7) >= NSTK;
    #pragma unroll
    for(int p=0;p<4;p++){
        #pragma unroll
        for(int lane=0; lane<2; lane++){
            int s = ty*8 + 2*p + lane;
            float* op = scores + ((size_t)bh*SS + s)*NSTK;
            float v8[8];
            #pragma unroll
            for(int j=0;j<8;j++){
                float d = lane ? lane1(acc[p][j]) : lane0(acc[p][j]);
                float sc = d / 5.656854249492381f;  // f32 div, round
                v8[j] = sc * gv[j];                  // f32 mul, round
            }
            if (!edge){
                *(float4*)(op + n0 + tx*8)     = make_float4(v8[0],v8[1],v8[2],v8[3]);
                *(float4*)(op + n0 + tx*8 + 4) = make_float4(v8[4],v8[5],v8[6],v8[7]);
            } else {
                #pragma unroll
                for(int j=0;j<8;j++){
                    int n = n0 + tx*8 + j;
                    if (n < NSTK) op[n] = v8[j];
                }
            }
        }
    }
}

// per-(b,h,s) row: exact top-200 (value desc, index asc), softmax, context.
// Round-11 proven version: plain histogram atomics (warp-aggregation schemes
// measured SLOWER on sm_103a — match_any and ballot-loop both regressed).
__global__ void __launch_bounds__(256) topk_kernel(const float* __restrict__ scores,
    const float* __restrict__ V, float* __restrict__ attn_out,
    float* __restrict__ attd_out, float* __restrict__ ctx)
{
    __shared__ float vals[NSTK];
    __shared__ unsigned hist[256];
    __shared__ unsigned long long cand[256];
    __shared__ float earr[256];
    __shared__ float red[256];
    __shared__ int   iarr[256];
    __shared__ float ctxp[8][32];
    __shared__ unsigned sh_prefix;
    __shared__ int sh_rem, sh_cnt;

    const int r = blockIdx.x;
    const int s = r & 127, h = (r>>7)&31, b = r>>12;
    const int tid = threadIdx.x;
    const float* rowp = scores + (size_t)r*NSTK;
    {   // vectorized row load: 6000 = 1500 float4
        const float4* rp4 = (const float4*)rowp;
        for (int i=tid; i<NSTK/4; i+=256)
            *(float4*)&vals[i*4] = rp4[i];
    }
    if (tid==0){ sh_prefix=0u; sh_rem=TOPK; }
    __syncthreads();

    // 4-pass radix select: exact key of 200th-largest
    #pragma unroll
    for (int pass=0; pass<4; pass++){
        const int shift = 24 - pass*8;
        hist[tid]=0u;
        __syncthreads();
        unsigned pref = sh_prefix;
        for (int i=tid;i<NSTK;i+=256){
            unsigned k = mono_f(vals[i]);
            unsigned hi = (pass==0) ? 0u : (k >> (shift+8));
            if (hi == pref)
                atomicAdd(&hist[(k>>shift)&0xFFu], 1u);
        }
        __syncthreads();
        if (tid==0){
            int rem = sh_rem; int bsel = 255;
            for (; bsel>0; bsel--){
                int c = (int)hist[bsel];
                if (c >= rem) break;
                rem -= c;
            }
            sh_prefix = (pref<<8) | (unsigned)bsel;
            sh_rem = rem;
        }
        __syncthreads();
    }
    const unsigned T = sh_prefix;
    if (tid==0) sh_cnt=0;
    cand[tid] = 0xFFFFFFFFFFFFFFFFull;
    __syncthreads();
    for (int i=tid;i<NSTK;i+=256){
        unsigned k = mono_f(vals[i]);
        if (k >= T){
            int p = atomicAdd(&sh_cnt,1);
            if (p < 256) cand[p] = (((unsigned long long)(~k))<<32) | (unsigned)i;
        }
    }
    __syncthreads();
    // bitonic sort 256 u64 ascending -> (value desc, index asc)
    for (int k2=2; k2<=256; k2<<=1){
        for (int j=k2>>1; j>0; j>>=1){
            int ixj = tid ^ j;
            if (ixj > tid){
                unsigned long long A=cand[tid], Bv=cand[ixj];
                bool up = ((tid & k2)==0);
                if (up ? (A > Bv) : (A < Bv)){ cand[tid]=Bv; cand[ixj]=A; }
            }
            __syncthreads();
        }
    }
    // softmax over top 200
    float v0 = unmono_f(~(unsigned)(cand[0]>>32));
    float e = 0.f; int idx = 0;
    if (tid < TOPK){
        unsigned long long c = cand[tid];
        idx = (int)(unsigned)(c & 0xFFFFFFFFull);
        float v = unmono_f(~(unsigned)(c>>32));
        e = expf(v - v0);
    }
    earr[tid]=e; red[tid]=e; iarr[tid]=idx;
    __syncthreads();
    for (int st=128; st>0; st>>=1){
        if (tid < st) red[tid] += red[tid+st];
        __syncthreads();
    }
    float inv = 1.0f/red[0];
    float a = e*inv;
    if (tid < TOPK){
        attn_out[(size_t)r*TOPK + tid] = a;
        if (s == SS-1) attd_out[(size_t)(b*NH + h)*TOPK + tid] = (float)idx;
    }
    __syncthreads();
    earr[tid] = a;
    __syncthreads();
    // context: c[d] = sum_k a_k * V[idx_k, h, d]
    int w = tid>>5, lane = tid&31;
    float accd = 0.f;
    for (int k2=w; k2<TOPK; k2+=8)
        accd = fmaf(earr[k2], V[(size_t)iarr[k2]*HID + h*HD + lane], accd);
    ctxp[w][lane]=accd;
    __syncthreads();
    if (tid < 32){
        float sum2 = 0.f;
        #pragma unroll
        for (int w2=0; w2<8; w2++) sum2 += ctxp[w2][tid];
        ctx[(size_t)(b*SS + s)*HID + h*HD + tid] = sum2;
    }
}

// out = LN(qf + oproj) * g + b
__global__ void __launch_bounds__(256) ln_kernel(const float* __restrict__ qf,
    const float* __restrict__ O, const float* __restrict__ g,
    const float* __restrict__ be, float* __restrict__ out)
{
    __shared__ float red[256];
    const int r = blockIdx.x, tid = threadIdx.x;
    float x[4];
    #pragma unroll
    for (int i=0;i<4;i++){
        int c = tid + i*256;
        x[i] = qf[(size_t)r*HID + c] + O[(size_t)r*HID + c];
    }
    float sm = x[0]+x[1]+x[2]+x[3];
    red[tid]=sm; __syncthreads();
    for (int st=128; st>0; st>>=1){ if (tid<st) red[tid]+=red[tid+st]; __syncthreads(); }
    float mu = red[0]*(1.0f/HID);
    __syncthreads();
    float vs = 0.f;
    #pragma unroll
    for (int i=0;i<4;i++){ float d=x[i]-mu; vs += d*d; }
    red[tid]=vs; __syncthreads();
    for (int st=128; st>0; st>>=1){ if (tid<st) red[tid]+=red[tid+st]; __syncthreads(); }
    float rstd = rsqrtf(red[0]*(1.0f/HID) + 1e-5f);
    #pragma unroll
    for (int i=0;i<4;i++){
        int c = tid + i*256;
        out[(size_t)r*HID + c] = (x[i]-mu)*rstd*g[c] + be[c];
    }
}

extern "C" void kernel_launch(void* const* d_in, const int* in_sizes, int n_in,
                              void* d_out, int out_size)
{
    const float* qf  = (const float*)d_in[0];
    const int*   qid = (const int*)  d_in[1];
    const float* emb = (const float*)d_in[2];
    const float* pW1 = (const float*)d_in[3];
    const float* pb1 = (const float*)d_in[4];
    const float* pW2 = (const float*)d_in[5];
    const float* pb2 = (const float*)d_in[6];
    const float* Wq  = (const float*)d_in[7];
    const float* bq  = (const float*)d_in[8];
    const float* Wk  = (const float*)d_in[9];
    const float* bk  = (const float*)d_in[10];
    const float* Wv  = (const float*)d_in[11];
    const float* bv  = (const float*)d_in[12];
    const float* Wo  = (const float*)d_in[13];
    const float* bo  = (const float*)d_in[14];
    const float* Wg1 = (const float*)d_in[15];
    const float* bg1 = (const float*)d_in[16];
    const float* Wg2 = (const float*)d_in[17];
    const float* bg2 = (const float*)d_in[18];
    const float* lng = (const float*)d_in[19];
    const float* lnb = (const float*)d_in[20];
    float* out = (float*)d_out;

    float *T1,*KV,*Kb,*Vb,*Hh,*Qm,*qc,*qcp,*gates,*scores,*ctx,*op;
    cudaGetSymbolAddress((void**)&T1,    g_T1);
    cudaGetSymbolAddress((void**)&KV,    g_KV);
    cudaGetSymbolAddress((void**)&Kb,    g_K);
    cudaGetSymbolAddress((void**)&Vb,    g_V);
    cudaGetSymbolAddress((void**)&Hh,    g_H);
    cudaGetSymbolAddress((void**)&Qm,    g_Q);
    cudaGetSymbolAddress((void**)&qc,    g_qc);
    cudaGetSymbolAddress((void**)&qcp,   g_qcp);
    cudaGetSymbolAddress((void**)&gates, g_gates);
    cudaGetSymbolAddress((void**)&scores,g_scores);
    cudaGetSymbolAddress((void**)&ctx,   g_ctx);
    cudaGetSymbolAddress((void**)&op,    g_op);

    const int GY = (NSTK + 127)/128;   // 47

    // embed_proj(stock_embed): T1 = gelu(E@pW1+pb1); KV = T1@pW2+pb2
    sgemm2<1><<<dim3(16,GY),256>>>(emb, pW1, pb1, T1, NSTK, EMB, HID);
    sgemm2<0><<<dim3(16,GY),256>>>(T1,  pW2, pb2, KV, NSTK, HID, HID);
    // K / V projections (score-critical serial chains)
    sgemm2<0><<<dim3(16,GY),256>>>(KV, Wk, bk, Kb, NSTK, HID, HID);
    sgemm2<0><<<dim3(16,GY),256>>>(KV, Wv, bv, Vb, NSTK, HID, HID);
    // Q projection: small-M path (M=512), double-buffered
    sgemm_s32<0><<<dim3(16,16),256>>>(qf, Wq, bq, Qm, BB*SS, HID, HID);
    // query_combined, qc-half serial chain (no bias — bias joins after kv-half)
    qc_kernel<<<BB,256>>>(qf, qid, KV, qc);
    qcp_kernel<<<BB,1024>>>(qc, Wg1, qcp);
    // full gate chain: continue qcp serially over kv-half, +bg1, gelu
    gateh2<<<dim3(16,GY,BB),256>>>(KV, Wg1 + (size_t)HID*HID, qcp, bg1, Hh);
    // gate stage 2: H @ Wg2 + bg2 -> sigmoid
    gates2_kernel<<<(BB*NSTK)/64,256>>>(Hh, Wg2, bg2, gates);
    // scores (two-step rounding: /sqrt(32) then *gate)
    scores2_kernel<<<dim3((NSTK+127)/128, BB*NH),256>>>(Qm, Kb, gates, scores);
    // top-k + softmax + context (+ attn / attended outputs)
    topk_kernel<<<NROWS,256>>>(scores, Vb, out + OUT_OFF_ATTN, out + OUT_OFF_ATTD, ctx);
    // output projection + residual + layernorm: small-M path (M=512), double-buffered
    sgemm_s32<0><<<dim3(16,16),256>>>(ctx, Wo, bo, op, BB*SS, HID, HID);
    ln_kernel<<<BB*SS,256>>>(qf, op, lng, lnb, out);
}